// round 1
// baseline (speedup 1.0000x reference)
#include <cuda_runtime.h>

#define B_ 2
#define N_ 512
#define IN_DIM 512
#define EMB 64
#define HID 128
#define NPOS 1025          // emb_table rows = 2*512+1
#define TP 128             // pairs (m values) per block

// ---------------- scratch (no cudaMalloc allowed) ----------------
__device__ float g_sl[B_ * N_ * EMB];      // s @ W_left + b_left
__device__ float g_sr[B_ * N_ * EMB];      // s @ W_right + b_right
__device__ float g_P[NPOS * HID];          // emb_table @ W1[64:128] + b1

// ---------------- packed f32x2 helpers (Blackwell) ----------------
__device__ __forceinline__ void fma2(unsigned long long& acc,
                                     unsigned long long a,
                                     unsigned long long b) {
    asm("fma.rn.f32x2 %0, %1, %2, %0;" : "+l"(acc) : "l"(a), "l"(b));
}
__device__ __forceinline__ unsigned long long dup2(float a) {
    unsigned long long r;
    asm("mov.b64 %0, {%1, %1};" : "=l"(r) : "f"(a));
    return r;
}
__device__ __forceinline__ float2 unpack2(unsigned long long v) {
    float2 f;
    asm("mov.b64 {%0, %1}, %2;" : "=f"(f.x), "=f"(f.y) : "l"(v));
    return f;
}

// ---------------- kernel 1: left/right projections ----------------
// grid = B*N blocks, 128 threads. threads 0..63 -> left, 64..127 -> right.
__global__ void proj_kernel(const float* __restrict__ s,
                            const float* __restrict__ Wl, const float* __restrict__ bl,
                            const float* __restrict__ Wr, const float* __restrict__ br) {
    __shared__ float srow[IN_DIM];
    const int r = blockIdx.x;
    const int t = threadIdx.x;
    for (int i = t; i < IN_DIM; i += 128) srow[i] = s[(size_t)r * IN_DIM + i];
    __syncthreads();

    const float* W;
    float acc;
    int col;
    if (t < EMB) { W = Wl; col = t;       acc = bl[col]; }
    else         { W = Wr; col = t - EMB; acc = br[col]; }
#pragma unroll 8
    for (int k = 0; k < IN_DIM; k++)
        acc = fmaf(srow[k], W[k * EMB + col], acc);

    if (t < EMB) g_sl[r * EMB + col] = acc;
    else         g_sr[r * EMB + col] = acc;
}

// ---------------- kernel 2: positional table P[dist][h] ----------------
// P = emb_table @ W1[64:128,:] + b1.   grid = 1025 blocks, 128 threads.
__global__ void pos_kernel(const float* __restrict__ emb,
                           const float* __restrict__ W1,
                           const float* __restrict__ b1) {
    __shared__ float erow[EMB];
    const int dist = blockIdx.x;
    const int h = threadIdx.x;
    if (h < EMB) erow[h] = emb[dist * EMB + h];
    __syncthreads();

    float acc = b1[h];
#pragma unroll
    for (int d = 0; d < EMB; d++)
        acc = fmaf(erow[d], W1[(EMB + d) * HID + h], acc);
    g_P[dist * HID + h] = acc;
}

// ---------------- kernel 3: main fused pairwise MLP ----------------
// Block = (b, n, m-tile of 128). Two smem-staged GEMMs with 8x8 / 8x4
// register tiles, packed f32x2 FMAs.
#define PITCH_A 132
#define PITCH_H 132
#define OFF_LS 0
#define OFF_W1 64
#define OFF_W2 (64 + 8192)
#define OFF_AT (64 + 8192 + 8192)
#define OFF_HS (OFF_AT + 64 * PITCH_A)
#define SMEM_FLOATS (OFF_HS + 128 * PITCH_H)

__global__ __launch_bounds__(256, 1)
void pair_main_kernel(const float* __restrict__ W1,
                      const float* __restrict__ W2,
                      const float* __restrict__ b2,
                      float* __restrict__ out) {
    extern __shared__ float sm[];
    float* Ls  = sm + OFF_LS;   // [64]        s_left row n
    float* W1s = sm + OFF_W1;   // [64][128]   W1_top
    float* W2s = sm + OFF_W2;   // [128][64]
    float* At  = sm + OFF_AT;   // [64][132]   A^T: At[d][p] = sr[m0+p][d]*Ls[d]
    float* Hs  = sm + OFF_HS;   // [128][132]  hidden activations

    const int tid = threadIdx.x;
    const int m0 = blockIdx.x * TP;
    const int n  = blockIdx.y;
    const int b  = blockIdx.z;

    if (tid < 64) Ls[tid] = g_sl[((size_t)b * N_ + n) * EMB + tid];
    for (int i = tid; i < 8192; i += 256) W1s[i] = W1[i];   // rows 0..63 of W1
    for (int i = tid; i < 8192; i += 256) W2s[i] = W2[i];
    __syncthreads();

    // build A^T
    const float* srbase = g_sr + ((size_t)b * N_ + m0) * EMB;
    for (int i = tid; i < TP * EMB; i += 256) {
        int p = i >> 6, d = i & 63;
        At[d * PITCH_A + p] = srbase[i] * Ls[d];
    }
    __syncthreads();

    // ---- phase A: Hs[128][128] = A[128][64] @ W1_top[64][128] ----
    {
        const int ty = tid >> 4, tx = tid & 15;
        const int prow = ty * 8, jcol = tx * 8;
        unsigned long long acc[8][4];
#pragma unroll
        for (int r = 0; r < 8; r++)
#pragma unroll
            for (int q = 0; q < 4; q++) acc[r][q] = 0ull;

#pragma unroll 4
        for (int k = 0; k < EMB; k++) {
            float4 a0 = *(const float4*)&At[k * PITCH_A + prow];
            float4 a1 = *(const float4*)&At[k * PITCH_A + prow + 4];
            unsigned long long bb[4];
#pragma unroll
            for (int q = 0; q < 4; q++)
                bb[q] = *(const unsigned long long*)&W1s[k * HID + jcol + 2 * q];
            float av[8] = {a0.x, a0.y, a0.z, a0.w, a1.x, a1.y, a1.z, a1.w};
#pragma unroll
            for (int r = 0; r < 8; r++) {
                unsigned long long ad = dup2(av[r]);
#pragma unroll
                for (int q = 0; q < 4; q++) fma2(acc[r][q], ad, bb[q]);
            }
        }
#pragma unroll
        for (int r = 0; r < 8; r++)
#pragma unroll
            for (int q = 0; q < 4; q++)
                *(unsigned long long*)&Hs[(prow + r) * PITCH_H + jcol + 2 * q] = acc[r][q];
    }
    __syncthreads();

    // ---- relu(H + P[dist]) in place; dist = n - (m0+p) + 512 in [1,1023] ----
    {
        const float* Pbase = g_P + (size_t)(n - m0 + 512) * HID;
        for (int i = tid; i < TP * HID; i += 256) {
            int p = i >> 7, j = i & 127;
            float v = Hs[p * PITCH_H + j] + __ldg(&Pbase[j - p * HID]);
            Hs[p * PITCH_H + j] = fmaxf(v, 0.0f);
        }
    }
    __syncthreads();

    // ---- phase B: out[128][64] = Hs[128][128] @ W2[128][64] + b2 ----
    {
        const int ty2 = tid >> 4, tx2 = tid & 15;
        const int prow2 = ty2 * 8, ocol = tx2 * 4;
        const float b2r0 = b2[ocol], b2r1 = b2[ocol + 1];
        const float b2r2 = b2[ocol + 2], b2r3 = b2[ocol + 3];

        unsigned long long acc[8][2];
#pragma unroll
        for (int r = 0; r < 8; r++) { acc[r][0] = 0ull; acc[r][1] = 0ull; }

#pragma unroll 2
        for (int j = 0; j < HID; j++) {
            unsigned long long w0 = *(const unsigned long long*)&W2s[j * EMB + ocol];
            unsigned long long w1 = *(const unsigned long long*)&W2s[j * EMB + ocol + 2];
#pragma unroll
            for (int r = 0; r < 8; r++) {
                unsigned long long hd = dup2(Hs[(prow2 + r) * PITCH_H + j]);
                fma2(acc[r][0], hd, w0);
                fma2(acc[r][1], hd, w1);
            }
        }

        float* obase = out + (((size_t)b * N_ + n) * N_ + m0) * EMB;
#pragma unroll
        for (int r = 0; r < 8; r++) {
            float2 v0 = unpack2(acc[r][0]);
            float2 v1 = unpack2(acc[r][1]);
            float4 o4 = make_float4(v0.x + b2r0, v0.y + b2r1, v1.x + b2r2, v1.y + b2r3);
            *(float4*)&obase[(size_t)(prow2 + r) * EMB + ocol] = o4;
        }
    }
}

// ---------------- launch ----------------
extern "C" void kernel_launch(void* const* d_in, const int* in_sizes, int n_in,
                              void* d_out, int out_size) {
    const float* s       = (const float*)d_in[0];
    const float* W_left  = (const float*)d_in[1];
    const float* b_left  = (const float*)d_in[2];
    const float* W_right = (const float*)d_in[3];
    const float* b_right = (const float*)d_in[4];
    const float* emb     = (const float*)d_in[5];
    const float* W1      = (const float*)d_in[6];
    const float* b1      = (const float*)d_in[7];
    const float* W2      = (const float*)d_in[8];
    const float* b2      = (const float*)d_in[9];
    float* out = (float*)d_out;

    proj_kernel<<<B_ * N_, 128>>>(s, W_left, b_left, W_right, b_right);
    pos_kernel<<<NPOS, 128>>>(emb, W1, b1);

    const size_t smem = SMEM_FLOATS * sizeof(float);  // 167,168 bytes
    cudaFuncSetAttribute(pair_main_kernel,
                         cudaFuncAttributeMaxDynamicSharedMemorySize, (int)smem);
    pair_main_kernel<<<dim3(N_ / TP, N_, B_), 256, smem>>>(W1, W2, b2, out);
}

// round 3
// speedup vs baseline: 2.3232x; 2.3232x over previous
#include <cuda_runtime.h>
#include <cuda_bf16.h>
#include <stdint.h>

#define B_ 2
#define N_ 512
#define IN_DIM 512
#define EMB 64
#define HID 128
#define NPOS 1025

// ---------------- device scratch (no cudaMalloc allowed) ----------------
__device__ float g_sl[B_ * N_ * EMB];          // s @ W_left + b_left
__device__ float g_sr[B_ * N_ * EMB];          // s @ W_right + b_right
__device__ float g_P[NPOS * HID];              // emb_table @ W1[64:128] + b1
__device__ unsigned short g_W1Th[HID * EMB];   // bf16-hi of W1_top^T [j][d]
__device__ unsigned short g_W1Tl[HID * EMB];   // bf16-lo
__device__ unsigned short g_W2Th[EMB * HID];   // bf16-hi of W2^T [o][j]
__device__ unsigned short g_W2Tl[EMB * HID];

// ---------------- helpers ----------------
__device__ __forceinline__ uint32_t smem_u32_of(const void* p) {
    uint32_t a;
    asm("{ .reg .u64 t; cvta.to.shared.u64 t, %1; cvt.u32.u64 %0, t; }"
        : "=r"(a) : "l"(p));
    return a;
}
__device__ __forceinline__ uint32_t pack_bf16(float e0, float e1) {
    __nv_bfloat162 t = __floats2bfloat162_rn(e0, e1);  // .x = e0 (low), .y = e1 (high)
    return *reinterpret_cast<uint32_t*>(&t);
}
// split pair into (hi_pair, lo_pair) bf16x2 words; low half = even element
__device__ __forceinline__ uint2 split2(float e0, float e1) {
    uint32_t hp = pack_bf16(e0, e1);
    float h0 = __uint_as_float(hp << 16);
    float h1 = __uint_as_float(hp & 0xFFFF0000u);
    uint32_t lp = pack_bf16(e0 - h0, e1 - h1);
    return make_uint2(hp, lp);
}
__device__ __forceinline__ void mma16816(float* c, const uint32_t* a, const uint32_t* b) {
    asm volatile(
        "mma.sync.aligned.m16n8k16.row.col.f32.bf16.bf16.f32 "
        "{%0,%1,%2,%3}, {%4,%5,%6,%7}, {%8,%9}, {%0,%1,%2,%3};"
        : "+f"(c[0]), "+f"(c[1]), "+f"(c[2]), "+f"(c[3])
        : "r"(a[0]), "r"(a[1]), "r"(a[2]), "r"(a[3]), "r"(b[0]), "r"(b[1]));
}
__device__ __forceinline__ void ldsm4(uint32_t* r, uint32_t addr) {
    asm volatile("ldmatrix.sync.aligned.m8n8.x4.shared.b16 {%0,%1,%2,%3}, [%4];"
                 : "=r"(r[0]), "=r"(r[1]), "=r"(r[2]), "=r"(r[3]) : "r"(addr));
}
__device__ __forceinline__ void ldsm2(uint32_t* r, uint32_t addr) {
    asm volatile("ldmatrix.sync.aligned.m8n8.x2.shared.b16 {%0,%1}, [%2];"
                 : "=r"(r[0]), "=r"(r[1]) : "r"(addr));
}

// ---------------- kernel 1: projections (tiled, smem-staged) ----------------
__global__ void proj2_kernel(const float* __restrict__ s,
                             const float* __restrict__ Wl, const float* __restrict__ bl,
                             const float* __restrict__ Wr, const float* __restrict__ br) {
    extern __shared__ float psm[];
    float* SsT = psm;              // [512][20] transposed s rows
    float* Wc  = psm + 512 * 20;   // [64][128] concat W k-tile

    const int t = threadIdx.x;
    const int r0 = blockIdx.x * 16;

    for (int i = t; i < 16 * IN_DIM; i += 256) {
        int row = i >> 9, k = i & 511;
        SsT[k * 20 + row] = s[(size_t)(r0 + row) * IN_DIM + k];
    }

    const int col = t & 127, rg = t >> 7;
    float acc[8];
    const float bias = (col < 64) ? bl[col] : br[col - 64];
#pragma unroll
    for (int r = 0; r < 8; r++) acc[r] = bias;
    __syncthreads();

    for (int kt = 0; kt < 8; kt++) {
        for (int i = t; i < 64 * 128; i += 256) {
            int k = i >> 7, c = i & 127;
            Wc[i] = (c < 64) ? Wl[(size_t)(kt * 64 + k) * 64 + c]
                             : Wr[(size_t)(kt * 64 + k) * 64 + (c - 64)];
        }
        __syncthreads();
#pragma unroll 4
        for (int k = 0; k < 64; k++) {
            float w = Wc[k * 128 + col];
            const float* sp = &SsT[(kt * 64 + k) * 20 + rg * 8];
            float4 a0 = *(const float4*)sp;
            float4 a1 = *(const float4*)(sp + 4);
            acc[0] += a0.x * w; acc[1] += a0.y * w; acc[2] += a0.z * w; acc[3] += a0.w * w;
            acc[4] += a1.x * w; acc[5] += a1.y * w; acc[6] += a1.z * w; acc[7] += a1.w * w;
        }
        __syncthreads();
    }
#pragma unroll
    for (int r = 0; r < 8; r++) {
        int row = r0 + rg * 8 + r;
        if (col < 64) g_sl[(size_t)row * 64 + col] = acc[r];
        else          g_sr[(size_t)row * 64 + (col - 64)] = acc[r];
    }
}

// ---------------- kernel 2: weight transposes + bf16 hi/lo split ----------------
__global__ void prep_kernel(const float* __restrict__ W1, const float* __restrict__ W2) {
    int i = blockIdx.x * 256 + threadIdx.x;
    if (i < HID * EMB) {
        {   // W1 top transposed: [j][d] = W1[d][j], d<64
            int j = i >> 6, d = i & 63;
            float w = W1[d * HID + j];
            unsigned short hs = __bfloat16_as_ushort(__float2bfloat16(w));
            float hf = __uint_as_float((uint32_t)hs << 16);
            unsigned short ls = __bfloat16_as_ushort(__float2bfloat16(w - hf));
            g_W1Th[i] = hs; g_W1Tl[i] = ls;
        }
        {   // W2 transposed: [o][j] = W2[j][o]
            int o = i & 63, jj = i >> 6;
            float w = W2[jj * EMB + o];
            unsigned short hs = __bfloat16_as_ushort(__float2bfloat16(w));
            float hf = __uint_as_float((uint32_t)hs << 16);
            unsigned short ls = __bfloat16_as_ushort(__float2bfloat16(w - hf));
            g_W2Th[o * HID + jj] = hs; g_W2Tl[o * HID + jj] = ls;
        }
    }
}

// ---------------- kernel 3: positional table ----------------
__global__ void pos_kernel(const float* __restrict__ emb,
                           const float* __restrict__ W1,
                           const float* __restrict__ b1) {
    __shared__ float erow[EMB];
    const int dist = blockIdx.x;
    const int h = threadIdx.x;
    if (h < EMB) erow[h] = emb[dist * EMB + h];
    __syncthreads();
    float acc = b1[h];
#pragma unroll
    for (int d = 0; d < EMB; d++)
        acc = fmaf(erow[d], W1[(EMB + d) * HID + h], acc);
    g_P[dist * HID + h] = acc;
}

// ---------------- main kernel: mma.sync bf16 hi/lo, one block per (b,n) ----------------
// smem byte offsets. W1 tiles: [128 j][72 bf16] stride 144B; W2: [64 o][136] stride 272B;
// A': [128 m][72] stride 144B.
#define OFF_SL   0
#define OFF_W1H  256
#define OFF_W1L  (OFF_W1H + 18432)
#define OFF_W2H  (OFF_W1L + 18432)
#define OFF_W2L  (OFF_W2H + 17408)
#define OFF_AH   (OFF_W2L + 17408)
#define OFF_AL   (OFF_AH + 18432)
#define SMEM_MAIN (OFF_AL + 18432)   // 108800 bytes

__global__ __launch_bounds__(256, 1)
void pair_mma_kernel(const float* __restrict__ b2, float* __restrict__ out) {
    extern __shared__ char sm[];
    const uint32_t smb = smem_u32_of(sm);
    const int tid = threadIdx.x;
    const int w = tid >> 5, l = tid & 31;
    const int n = blockIdx.x, b = blockIdx.y;

    float* sl = (float*)(sm + OFF_SL);
    if (tid < 64) sl[tid] = g_sl[((size_t)b * N_ + n) * EMB + tid];

    // copy pre-split weights into padded smem (8B vectors)
    for (int i = tid; i < 2048; i += 256) {
        int j = i >> 4, d8 = (i & 15) * 8;                 // byte col offset
        *(uint2*)(sm + OFF_W1H + j * 144 + d8) = ((const uint2*)g_W1Th)[i];
        *(uint2*)(sm + OFF_W1L + j * 144 + d8) = ((const uint2*)g_W1Tl)[i];
    }
    for (int i = tid; i < 2048; i += 256) {
        int o = i >> 5, j8 = (i & 31) * 8;
        *(uint2*)(sm + OFF_W2H + o * 272 + j8) = ((const uint2*)g_W2Th)[i];
        *(uint2*)(sm + OFF_W2L + o * 272 + j8) = ((const uint2*)g_W2Tl)[i];
    }
    __syncthreads();

    // per-thread ldmatrix base addresses
    const int rowsel = l & 7, half = (l >> 3) & 1;
    const uint32_t preB1 = smb + OFF_W1H + rowsel * 144 + half * 16;
    const uint32_t preB2 = smb + OFF_W2H + rowsel * 272 + half * 16;
    const int arow = (l & 15);                    // row within 16
    const uint32_t preA = smb + OFF_AH + (16 * w + arow) * 144 + (l >> 4) * 16;

    // per-thread output-column biases (loop-invariant)
    float2 bias[8];
#pragma unroll
    for (int q = 0; q < 8; q++)
        bias[q] = __ldg((const float2*)(b2 + 8 * q + (l & 3) * 2));

    for (int mt = 0; mt < 4; mt++) {
        const int m0 = mt * 128;

        // ---- build A'[m][d] = SR[m][d] * sl[d], split hi/lo ----
        {
            const int row = tid >> 1, c0 = (tid & 1) * 32;
            const float4* s4 = (const float4*)(g_sr + ((size_t)(b * N_ + m0 + row)) * EMB + c0);
            const float4* sl4 = (const float4*)(sl + c0);
            char* dsth = sm + OFF_AH + row * 144 + c0 * 2;
            char* dstl = sm + OFF_AL + row * 144 + c0 * 2;
#pragma unroll
            for (int i = 0; i < 4; i++) {
                float4 v0 = s4[2 * i], v1 = s4[2 * i + 1];
                float4 w0 = sl4[2 * i], w1 = sl4[2 * i + 1];
                v0.x *= w0.x; v0.y *= w0.y; v0.z *= w0.z; v0.w *= w0.w;
                v1.x *= w1.x; v1.y *= w1.y; v1.z *= w1.z; v1.w *= w1.w;
                uint2 p0 = split2(v0.x, v0.y), p1 = split2(v0.z, v0.w);
                uint2 p2 = split2(v1.x, v1.y), p3 = split2(v1.z, v1.w);
                *(uint4*)(dsth + i * 16) = make_uint4(p0.x, p1.x, p2.x, p3.x);
                *(uint4*)(dstl + i * 16) = make_uint4(p0.y, p1.y, p2.y, p3.y);
            }
        }
        __syncthreads();

        // ---- GEMM1: H[128,128] = A'[128,64] @ W1T^T  (3-term hi/lo) ----
        float D1[16][4];
#pragma unroll
        for (int q = 0; q < 16; q++)
#pragma unroll
            for (int e = 0; e < 4; e++) D1[q][e] = 0.0f;

#pragma unroll
        for (int t = 0; t < 4; t++) {
            uint32_t ah[4], al[4];
            ldsm4(ah, preA + t * 32);
            ldsm4(al, preA + 18432 + t * 32);
#pragma unroll
            for (int q = 0; q < 16; q++) {
                uint32_t bh[2], bl[2];
                ldsm2(bh, preB1 + q * 1152 + t * 32);
                ldsm2(bl, preB1 + 18432 + q * 1152 + t * 32);
                mma16816(D1[q], ah, bh);
                mma16816(D1[q], ah, bl);
                mma16816(D1[q], al, bh);
            }
        }
        __syncthreads();   // A' consumed; next tile may rebuild

        // ---- relu(H + P[dist]) in registers ----
        const int m_t = m0 + 16 * w + (l >> 2);
        {
            const float* P0 = g_P + (size_t)(n - m_t + 512) * HID;
            const float* P1 = P0 - 8 * HID;   // row m_t+8
#pragma unroll
            for (int q = 0; q < 16; q++) {
                const int jc = 8 * q + (l & 3) * 2;
                float2 p0 = __ldg((const float2*)(P0 + jc));
                float2 p1 = __ldg((const float2*)(P1 + jc));
                D1[q][0] = fmaxf(D1[q][0] + p0.x, 0.0f);
                D1[q][1] = fmaxf(D1[q][1] + p0.y, 0.0f);
                D1[q][2] = fmaxf(D1[q][2] + p1.x, 0.0f);
                D1[q][3] = fmaxf(D1[q][3] + p1.y, 0.0f);
            }
        }

        // ---- GEMM2: out[128,64] = Hrelu[128,128] @ W2  (A from registers) ----
        float D2[8][4];
#pragma unroll
        for (int q = 0; q < 8; q++)
#pragma unroll
            for (int e = 0; e < 4; e++) D2[q][e] = 0.0f;

#pragma unroll
        for (int t = 0; t < 8; t++) {
            uint32_t ah2[4], al2[4];
            {
                uint2 s0 = split2(D1[2 * t][0],     D1[2 * t][1]);
                uint2 s1 = split2(D1[2 * t][2],     D1[2 * t][3]);
                uint2 s2 = split2(D1[2 * t + 1][0], D1[2 * t + 1][1]);
                uint2 s3 = split2(D1[2 * t + 1][2], D1[2 * t + 1][3]);
                ah2[0] = s0.x; al2[0] = s0.y;
                ah2[1] = s1.x; al2[1] = s1.y;
                ah2[2] = s2.x; al2[2] = s2.y;
                ah2[3] = s3.x; al2[3] = s3.y;
            }
#pragma unroll
            for (int q = 0; q < 8; q++) {
                uint32_t bh[2], bl[2];
                ldsm2(bh, preB2 + q * 2176 + t * 32);
                ldsm2(bl, preB2 + 17408 + q * 2176 + t * 32);
                mma16816(D2[q], ah2, bh);
                mma16816(D2[q], ah2, bl);
                mma16816(D2[q], al2, bh);
            }
        }

        // ---- epilogue: + b2, store fp32 ----
        {
            float* ob = out + (((size_t)b * N_ + n) * N_ + m_t) * EMB;
#pragma unroll
            for (int q = 0; q < 8; q++) {
                const int oc = 8 * q + (l & 3) * 2;
                *(float2*)(ob + oc) =
                    make_float2(D2[q][0] + bias[q].x, D2[q][1] + bias[q].y);
                *(float2*)(ob + 8 * EMB + oc) =
                    make_float2(D2[q][2] + bias[q].x, D2[q][3] + bias[q].y);
            }
        }
    }
}

// ---------------- launch ----------------
extern "C" void kernel_launch(void* const* d_in, const int* in_sizes, int n_in,
                              void* d_out, int out_size) {
    const float* s       = (const float*)d_in[0];
    const float* W_left  = (const float*)d_in[1];
    const float* b_left  = (const float*)d_in[2];
    const float* W_right = (const float*)d_in[3];
    const float* b_right = (const float*)d_in[4];
    const float* emb     = (const float*)d_in[5];
    const float* W1      = (const float*)d_in[6];
    const float* b1      = (const float*)d_in[7];
    const float* W2      = (const float*)d_in[8];
    const float* b2      = (const float*)d_in[9];
    float* out = (float*)d_out;

    cudaFuncSetAttribute(proj2_kernel,
                         cudaFuncAttributeMaxDynamicSharedMemorySize, 73728);
    cudaFuncSetAttribute(pair_mma_kernel,
                         cudaFuncAttributeMaxDynamicSharedMemorySize, SMEM_MAIN);

    proj2_kernel<<<64, 256, 73728>>>(s, W_left, b_left, W_right, b_right);
    prep_kernel<<<32, 256>>>(W1, W2);
    pos_kernel<<<NPOS, 128>>>(emb, W1, b1);
    pair_mma_kernel<<<dim3(N_, B_), 256, SMEM_MAIN>>>(b2, out);
}